// round 7
// baseline (speedup 1.0000x reference)
#include <cuda_runtime.h>
#include <cuda_fp16.h>
#include <cstdint>

#define NN 100000
#define EE 3200000
#define NC 64
#define TOPK 16
#define NHID 128
#define DEG 6
#define SCAN_BS 1024
#define SCAN_NB ((NN + SCAN_BS - 1) / SCAN_BS)   // 98

#define QSCALE (32.0f * 32767.0f)
#define QDEC   (1.0f / (32.0f * 32767.0f))

// ---------------- device scratch (static allocation only) ----------------
__device__ int      g_count[NN];            // zero at load; self-restored each call
__device__ int      g_rowstart[NN + 1];
__device__ int      g_cursor[NN];
__device__ int      g_aggr[SCAN_NB];
__device__ int      g_incl[SCAN_NB];
__device__ int      g_flag[SCAN_NB];
__device__ __align__(16) unsigned g_csrp[EE];   // packed: col<<15 | q15
__device__ __align__(16) __half g_xh[(size_t)NN * NC];
__device__ __align__(16) __half g_curh[5][(size_t)NN * NC];
__device__ float g_weight[NN * DEG];

// ---------------- hist (+ reset scan flags for this call) ----------------
__global__ void k_hist(const int* __restrict__ er) {
    int i = blockIdx.x * blockDim.x + threadIdx.x;
    if (i < SCAN_NB) g_flag[i] = 0;
    if (i < EE) atomicAdd(&g_count[er[i]], 1);
}

// ------- single-pass scan (decoupled lookback) + x -> fp16 conversion -------
__global__ void __launch_bounds__(SCAN_BS) k_scan(const float* __restrict__ x) {
    __shared__ int sh[SCAN_BS];
    __shared__ int s_prefix;
    int b = blockIdx.x, t = threadIdx.x;
    int i = b * SCAN_BS + t;

    int v = (i < NN) ? g_count[i] : 0;
    if (i < NN) g_count[i] = 0;
    sh[t] = v;
    __syncthreads();
    for (int o = 1; o < SCAN_BS; o <<= 1) {
        int tt = (t >= o) ? sh[t - o] : 0;
        __syncthreads();
        sh[t] += tt;
        __syncthreads();
    }
    int total = sh[SCAN_BS - 1];

    if (t == 0) {
        g_aggr[b] = total;
        __threadfence();
        g_flag[b] = 1;
        int pfx = 0;
        for (int j = b - 1; j >= 0; j--) {
            int f;
            do { f = ((volatile int*)g_flag)[j]; } while (f == 0);
            if (f == 2) { pfx += ((volatile int*)g_incl)[j]; break; }
            pfx += ((volatile int*)g_aggr)[j];
        }
        g_incl[b] = pfx + total;
        __threadfence();
        g_flag[b] = 2;
        s_prefix = pfx;
        if (b == 0) g_rowstart[NN] = EE;
    }
    __syncthreads();

    if (i < NN) {
        int r = s_prefix + sh[t] - v;
        g_rowstart[i] = r;
        g_cursor[i]   = r;
    }

    // fused: convert this block's rows of x to fp16
    size_t base = (size_t)b * SCAN_BS * NC;
    int nrows = NN - b * SCAN_BS;
    if (nrows > SCAN_BS) nrows = SCAN_BS;
    if (nrows > 0) {
        int nquad = nrows * NC / 4;
        for (int k = t; k < nquad; k += SCAN_BS) {
            float4 f = *(const float4*)(x + base + (size_t)k * 4);
            *(__half2*)(g_xh + base + (size_t)k * 4)     = __floats2half2_rn(f.x, f.y);
            *(__half2*)(g_xh + base + (size_t)k * 4 + 2) = __floats2half2_rn(f.z, f.w);
        }
    }
}

// ------- gating: softmax -> top16 -> MLP -> hop weights -------
__global__ void k_gating(const float* __restrict__ x,
                         const float* __restrict__ W1, const float* __restrict__ b1,
                         const float* __restrict__ W2, const float* __restrict__ b2) {
    int warp = (blockIdx.x * blockDim.x + threadIdx.x) >> 5;
    if (warp >= NN) return;
    int lane = threadIdx.x & 31;

    float2 xv = *(const float2*)(x + (size_t)warp * NC + 2 * lane);

    float m = fmaxf(xv.x, xv.y);
    #pragma unroll
    for (int o = 16; o; o >>= 1) m = fmaxf(m, __shfl_xor_sync(~0u, m, o));
    float e0 = __expf(xv.x - m), e1 = __expf(xv.y - m);
    float s = e0 + e1;
    #pragma unroll
    for (int o = 16; o; o >>= 1) s += __shfl_xor_sync(~0u, s, o);
    float inv = 1.0f / s;
    float a0 = e0 * inv, a1 = e1 * inv;

    float tk[TOPK];
    #pragma unroll
    for (int i = 0; i < TOPK; i++) {
        float lv; int li;
        if (a0 >= a1) { lv = a0; li = 2 * lane; } else { lv = a1; li = 2 * lane + 1; }
        #pragma unroll
        for (int o = 16; o; o >>= 1) {
            float ov = __shfl_xor_sync(~0u, lv, o);
            int   oi = __shfl_xor_sync(~0u, li, o);
            if (ov > lv || (ov == lv && oi < li)) { lv = ov; li = oi; }
        }
        tk[i] = lv;
        if ((li >> 1) == lane) { if (li & 1) a1 = -1.0f; else a0 = -1.0f; }
    }

    float h[4];
    #pragma unroll
    for (int j = 0; j < 4; j++) {
        int r = lane + 32 * j;
        float acc = b1[r];
        #pragma unroll
        for (int k = 0; k < TOPK; k++) acc += tk[k] * __ldg(&W1[r * TOPK + k]);
        h[j] = (acc >= 0.0f) ? acc : 0.1f * acc;
    }

    float lg[DEG];
    #pragma unroll
    for (int d = 0; d < DEG; d++) {
        float acc = 0.0f;
        #pragma unroll
        for (int j = 0; j < 4; j++) acc += h[j] * __ldg(&W2[d * NHID + lane + 32 * j]);
        #pragma unroll
        for (int o = 16; o; o >>= 1) acc += __shfl_xor_sync(~0u, acc, o);
        lg[d] = acc + b2[d];
    }

    float mm = lg[0];
    #pragma unroll
    for (int d = 1; d < DEG; d++) mm = fmaxf(mm, lg[d]);
    float ss = 0.0f;
    #pragma unroll
    for (int d = 0; d < DEG; d++) { lg[d] = __expf(lg[d] - mm); ss += lg[d]; }
    float invs = 1.0f / ss;
    if (lane < DEG) g_weight[warp * DEG + lane] = lg[lane] * invs;
}

// ---------------- scatter: packed 4-byte CSR entries ----------------
__global__ void k_scatter(const int* __restrict__ er,
                          const int* __restrict__ ec,
                          const float* __restrict__ ev) {
    int i = blockIdx.x * blockDim.x + threadIdx.x;
    if (i >= EE) return;
    int pos = atomicAdd(&g_cursor[er[i]], 1);
    unsigned q = (unsigned)__float2int_rn(ev[i] * QSCALE);   // 0..32767
    g_csrp[pos] = ((unsigned)ec[i] << 15) | q;
}

// -------- SpMM gather: fp16 features, fp32 accum, packed CSR --------
__device__ __forceinline__ void mac8(float* acc, uint4 raw, float v) {
    float2 f0 = __half22float2(*(__half2*)&raw.x);
    float2 f1 = __half22float2(*(__half2*)&raw.y);
    float2 f2 = __half22float2(*(__half2*)&raw.z);
    float2 f3 = __half22float2(*(__half2*)&raw.w);
    acc[0] += v * f0.x; acc[1] += v * f0.y;
    acc[2] += v * f1.x; acc[3] += v * f1.y;
    acc[4] += v * f2.x; acc[5] += v * f2.y;
    acc[6] += v * f3.x; acc[7] += v * f3.y;
}

__device__ __forceinline__ void edge1(float* acc, const __half* cur, int sub, unsigned p) {
    int   col = (int)(p >> 15);
    float v   = (float)(p & 0x7FFFu) * QDEC;
    uint4 r = *(const uint4*)(cur + (size_t)col * NC + sub * 8);
    mac8(acc, r, v);
}

__global__ void __launch_bounds__(256) k_spmm(int srcsel, int dstsel) {
    int gtid = blockIdx.x * blockDim.x + threadIdx.x;
    int row = gtid >> 3;                 // 8 lanes per row
    if (row >= NN) return;
    int sub = threadIdx.x & 7;

    const __half* __restrict__ cur = (srcsel < 0) ? g_xh : g_curh[srcsel];
    __half* __restrict__ next = g_curh[dstsel];

    int s = g_rowstart[row], e = g_rowstart[row + 1];
    float acc[8];
    #pragma unroll
    for (int j = 0; j < 8; j++) acc[j] = 0.0f;

    int i = s;
    while ((i & 3) && i < e) {           // peel to 16B boundary for uint4 csr loads
        edge1(acc, cur, sub, __ldg(&g_csrp[i]));
        i++;
    }
    for (; i + 8 <= e; i += 8) {         // 2x uint4 csr (8 edges) + 8 feature loads
        uint4 p0 = __ldg((const uint4*)&g_csrp[i]);
        uint4 p1 = __ldg((const uint4*)&g_csrp[i + 4]);
        uint4 r0 = *(const uint4*)(cur + (size_t)(p0.x >> 15) * NC + sub * 8);
        uint4 r1 = *(const uint4*)(cur + (size_t)(p0.y >> 15) * NC + sub * 8);
        uint4 r2 = *(const uint4*)(cur + (size_t)(p0.z >> 15) * NC + sub * 8);
        uint4 r3 = *(const uint4*)(cur + (size_t)(p0.w >> 15) * NC + sub * 8);
        uint4 r4 = *(const uint4*)(cur + (size_t)(p1.x >> 15) * NC + sub * 8);
        uint4 r5 = *(const uint4*)(cur + (size_t)(p1.y >> 15) * NC + sub * 8);
        uint4 r6 = *(const uint4*)(cur + (size_t)(p1.z >> 15) * NC + sub * 8);
        uint4 r7 = *(const uint4*)(cur + (size_t)(p1.w >> 15) * NC + sub * 8);
        mac8(acc, r0, (float)(p0.x & 0x7FFFu) * QDEC);
        mac8(acc, r1, (float)(p0.y & 0x7FFFu) * QDEC);
        mac8(acc, r2, (float)(p0.z & 0x7FFFu) * QDEC);
        mac8(acc, r3, (float)(p0.w & 0x7FFFu) * QDEC);
        mac8(acc, r4, (float)(p1.x & 0x7FFFu) * QDEC);
        mac8(acc, r5, (float)(p1.y & 0x7FFFu) * QDEC);
        mac8(acc, r6, (float)(p1.z & 0x7FFFu) * QDEC);
        mac8(acc, r7, (float)(p1.w & 0x7FFFu) * QDEC);
    }
    for (; i < e; i++) {
        edge1(acc, cur, sub, __ldg(&g_csrp[i]));
    }

    size_t off = (size_t)row * NC + sub * 8;
    uint4 packed;
    __half2* ph = (__half2*)&packed;
    ph[0] = __floats2half2_rn(acc[0], acc[1]);
    ph[1] = __floats2half2_rn(acc[2], acc[3]);
    ph[2] = __floats2half2_rn(acc[4], acc[5]);
    ph[3] = __floats2half2_rn(acc[6], acc[7]);
    *(uint4*)(next + off) = packed;
}

// ------- final: out = w0*x + sum_h w_h*cur_h, then log_softmax -------
__global__ void k_final(const float* __restrict__ x, float* __restrict__ dout) {
    int warp = (blockIdx.x * blockDim.x + threadIdx.x) >> 5;
    if (warp >= NN) return;
    int lane = threadIdx.x & 31;
    size_t off = (size_t)warp * NC + 2 * lane;

    float w[DEG];
    #pragma unroll
    for (int d = 0; d < DEG; d++) w[d] = __ldg(&g_weight[warp * DEG + d]);

    float2 xv = *(const float2*)(x + off);
    float tx = w[0] * xv.x, ty = w[0] * xv.y;
    #pragma unroll
    for (int h = 0; h < 5; h++) {
        float2 c = __half22float2(*(const __half2*)(g_curh[h] + off));
        tx += w[h + 1] * c.x;
        ty += w[h + 1] * c.y;
    }

    float m = fmaxf(tx, ty);
    #pragma unroll
    for (int o = 16; o; o >>= 1) m = fmaxf(m, __shfl_xor_sync(~0u, m, o));
    float s = __expf(tx - m) + __expf(ty - m);
    #pragma unroll
    for (int o = 16; o; o >>= 1) s += __shfl_xor_sync(~0u, s, o);
    float l = m + __logf(s);
    *(float2*)(dout + off) = make_float2(tx - l, ty - l);
}

// ---------------- launch ----------------
extern "C" void kernel_launch(void* const* d_in, const int* in_sizes, int n_in,
                              void* d_out, int out_size) {
    const float* x  = (const float*)d_in[0];
    const int*   er = (const int*)d_in[1];
    const int*   ec = (const int*)d_in[2];
    const float* ev = (const float*)d_in[3];
    const float* W1 = (const float*)d_in[4];
    const float* b1 = (const float*)d_in[5];
    const float* W2 = (const float*)d_in[6];
    const float* b2 = (const float*)d_in[7];
    float* out = (float*)d_out;

    k_hist<<<(EE + 255) / 256, 256>>>(er);                        // idx 0
    k_scan<<<SCAN_NB, SCAN_BS>>>(x);                              // idx 1
    k_gating<<<(NN * 32 + 255) / 256, 256>>>(x, W1, b1, W2, b2);  // idx 2
    k_scatter<<<(EE + 255) / 256, 256>>>(er, ec, ev);             // idx 3 <- profiled

    k_spmm<<<(NN * 8 + 255) / 256, 256>>>(-1, 0);                 // idx 4
    k_spmm<<<(NN * 8 + 255) / 256, 256>>>(0, 1);                  // idx 5
    k_spmm<<<(NN * 8 + 255) / 256, 256>>>(1, 2);                  // idx 6
    k_spmm<<<(NN * 8 + 255) / 256, 256>>>(2, 3);                  // idx 7
    k_spmm<<<(NN * 8 + 255) / 256, 256>>>(3, 4);                  // idx 8

    k_final<<<(NN * 32 + 255) / 256, 256>>>(x, out);              // idx 9
}

// round 8
// speedup vs baseline: 1.1306x; 1.1306x over previous
#include <cuda_runtime.h>
#include <cuda_fp16.h>
#include <cstdint>

#define NN 100000
#define EE 3200000
#define NC 64
#define TOPK 16
#define NHID 128
#define DEG 6
#define SCAN_BS 1024
#define SCAN_NB ((NN + SCAN_BS - 1) / SCAN_BS)   // 98

// ---------------- device scratch (static allocation only) ----------------
__device__ int   g_count[NN];            // zero at load; self-restored each call
__device__ int   g_rowstart[NN + 1];
__device__ int   g_cursor[NN];
__device__ int   g_aggr[SCAN_NB];
__device__ int   g_incl[SCAN_NB];
__device__ int   g_flag[SCAN_NB];
__device__ __align__(16) int2 g_csr[EE]; // (col, val bits fp32)
__device__ __align__(16) __half g_xh[(size_t)NN * NC];
__device__ __align__(16) __half g_curh[5][(size_t)NN * NC];
__device__ float g_weight[NN * DEG];

// ---------------- hist (+ reset scan flags for this call) ----------------
__global__ void k_hist(const int* __restrict__ er) {
    int i = blockIdx.x * blockDim.x + threadIdx.x;
    if (i < SCAN_NB) g_flag[i] = 0;
    if (i < EE) atomicAdd(&g_count[er[i]], 1);
}

// ------- single-pass scan (decoupled lookback) + x -> fp16 conversion -------
__global__ void __launch_bounds__(SCAN_BS) k_scan(const float* __restrict__ x) {
    __shared__ int sh[SCAN_BS];
    __shared__ int s_prefix;
    int b = blockIdx.x, t = threadIdx.x;
    int i = b * SCAN_BS + t;

    int v = (i < NN) ? g_count[i] : 0;
    if (i < NN) g_count[i] = 0;
    sh[t] = v;
    __syncthreads();
    for (int o = 1; o < SCAN_BS; o <<= 1) {
        int tt = (t >= o) ? sh[t - o] : 0;
        __syncthreads();
        sh[t] += tt;
        __syncthreads();
    }
    int total = sh[SCAN_BS - 1];

    if (t == 0) {
        g_aggr[b] = total;
        __threadfence();
        g_flag[b] = 1;
        int pfx = 0;
        for (int j = b - 1; j >= 0; j--) {
            int f;
            do { f = ((volatile int*)g_flag)[j]; } while (f == 0);
            if (f == 2) { pfx += ((volatile int*)g_incl)[j]; break; }
            pfx += ((volatile int*)g_aggr)[j];
        }
        g_incl[b] = pfx + total;
        __threadfence();
        g_flag[b] = 2;
        s_prefix = pfx;
        if (b == 0) g_rowstart[NN] = EE;
    }
    __syncthreads();

    if (i < NN) {
        int r = s_prefix + sh[t] - v;
        g_rowstart[i] = r;
        g_cursor[i]   = r;
    }

    // fused: convert this block's rows of x to fp16
    size_t base = (size_t)b * SCAN_BS * NC;
    int nrows = NN - b * SCAN_BS;
    if (nrows > SCAN_BS) nrows = SCAN_BS;
    if (nrows > 0) {
        int nquad = nrows * NC / 4;
        for (int k = t; k < nquad; k += SCAN_BS) {
            float4 f = *(const float4*)(x + base + (size_t)k * 4);
            *(__half2*)(g_xh + base + (size_t)k * 4)     = __floats2half2_rn(f.x, f.y);
            *(__half2*)(g_xh + base + (size_t)k * 4 + 2) = __floats2half2_rn(f.z, f.w);
        }
    }
}

// ---------------- scatter ----------------
__global__ void k_scatter(const int* __restrict__ er,
                          const int* __restrict__ ec,
                          const float* __restrict__ ev) {
    int i = blockIdx.x * blockDim.x + threadIdx.x;
    if (i >= EE) return;
    int pos = atomicAdd(&g_cursor[er[i]], 1);
    g_csr[pos] = make_int2(ec[i], __float_as_int(ev[i]));
}

// ------- gating: softmax -> bitonic top16 -> MLP -> hop weights -------
__global__ void k_gating(const float* __restrict__ x,
                         const float* __restrict__ W1, const float* __restrict__ b1,
                         const float* __restrict__ W2, const float* __restrict__ b2) {
    int warp = (blockIdx.x * blockDim.x + threadIdx.x) >> 5;
    if (warp >= NN) return;
    int lane = threadIdx.x & 31;

    float2 xv = *(const float2*)(x + (size_t)warp * NC + 2 * lane);

    // softmax over 64
    float m = fmaxf(xv.x, xv.y);
    #pragma unroll
    for (int o = 16; o; o >>= 1) m = fmaxf(m, __shfl_xor_sync(~0u, m, o));
    float e0 = __expf(xv.x - m), e1 = __expf(xv.y - m);
    float s = e0 + e1;
    #pragma unroll
    for (int o = 16; o; o >>= 1) s += __shfl_xor_sync(~0u, s, o);
    float inv = 1.0f / s;
    float a = e0 * inv, b = e1 * inv;   // vidx 2*lane, 2*lane+1

    // bitonic sort of 64 values, descending (values only — ties irrelevant
    // since only sorted VALUES feed W1, identical under any tie order)
    #pragma unroll
    for (int k = 2; k <= 64; k <<= 1) {
        #pragma unroll
        for (int j = k >> 1; j > 0; j >>= 1) {
            if (j >= 2) {
                float pa = __shfl_xor_sync(~0u, a, j >> 1);
                float pb = __shfl_xor_sync(~0u, b, j >> 1);
                int i0 = 2 * lane, i1 = 2 * lane + 1;
                bool up  = ((i0 & k) != 0);           // same for i1 (k>=4 here)
                bool km0 = (((i0 & j) == 0) != up);   // keep max?
                bool km1 = (((i1 & j) == 0) != up);
                a = km0 ? fmaxf(a, pa) : fminf(a, pa);
                b = km1 ? fmaxf(b, pb) : fminf(b, pb);
            } else {
                bool up = (((2 * lane) & k) != 0);
                float mx = fmaxf(a, b), mn = fminf(a, b);
                a = up ? mn : mx;
                b = up ? mx : mn;
            }
        }
    }

    // broadcast top-16 (vidx 0..15 live in lanes 0..7)
    float tk[TOPK];
    #pragma unroll
    for (int q = 0; q < 8; q++) {
        tk[2 * q]     = __shfl_sync(~0u, a, q);
        tk[2 * q + 1] = __shfl_sync(~0u, b, q);
    }

    // layer 1
    float h[4];
    #pragma unroll
    for (int j = 0; j < 4; j++) {
        int r = lane + 32 * j;
        float acc = b1[r];
        #pragma unroll
        for (int k = 0; k < TOPK; k++) acc += tk[k] * __ldg(&W1[r * TOPK + k]);
        h[j] = (acc >= 0.0f) ? acc : 0.1f * acc;
    }

    // layer 2
    float lg[DEG];
    #pragma unroll
    for (int d = 0; d < DEG; d++) {
        float acc = 0.0f;
        #pragma unroll
        for (int j = 0; j < 4; j++) acc += h[j] * __ldg(&W2[d * NHID + lane + 32 * j]);
        #pragma unroll
        for (int o = 16; o; o >>= 1) acc += __shfl_xor_sync(~0u, acc, o);
        lg[d] = acc + b2[d];
    }

    // softmax over 6 hops
    float mm = lg[0];
    #pragma unroll
    for (int d = 1; d < DEG; d++) mm = fmaxf(mm, lg[d]);
    float ss = 0.0f;
    #pragma unroll
    for (int d = 0; d < DEG; d++) { lg[d] = __expf(lg[d] - mm); ss += lg[d]; }
    float invs = 1.0f / ss;
    if (lane < DEG) g_weight[warp * DEG + lane] = lg[lane] * invs;
}

// -------- SpMM gather: fp16 features, HFMA2 fp16 accumulation --------
__device__ __forceinline__ void mach(__half2* acc, uint4 raw, __half2 vh) {
    acc[0] = __hfma2(*(__half2*)&raw.x, vh, acc[0]);
    acc[1] = __hfma2(*(__half2*)&raw.y, vh, acc[1]);
    acc[2] = __hfma2(*(__half2*)&raw.z, vh, acc[2]);
    acc[3] = __hfma2(*(__half2*)&raw.w, vh, acc[3]);
}

__global__ void __launch_bounds__(256) k_spmm(int srcsel, int dstsel) {
    int gtid = blockIdx.x * blockDim.x + threadIdx.x;
    int row = gtid >> 3;                 // 8 lanes per row
    if (row >= NN) return;
    int sub = threadIdx.x & 7;

    const __half* __restrict__ cur = (srcsel < 0) ? g_xh : g_curh[srcsel];
    __half* __restrict__ next = g_curh[dstsel];

    int s = g_rowstart[row], e = g_rowstart[row + 1];
    __half2 acc[4];
    #pragma unroll
    for (int j = 0; j < 4; j++) acc[j] = __floats2half2_rn(0.f, 0.f);

    int i = s;
    if ((i & 1) && i < e) {              // peel to 16B boundary for int4 csr loads
        int2 e0 = __ldg(&g_csr[i]);
        uint4 r0 = *(const uint4*)(cur + (size_t)e0.x * NC + sub * 8);
        mach(acc, r0, __float2half2_rn(__int_as_float(e0.y)));
        i++;
    }
    for (; i + 8 <= e; i += 8) {
        int4 p0 = __ldg((const int4*)&g_csr[i]);
        int4 p1 = __ldg((const int4*)&g_csr[i + 2]);
        int4 p2 = __ldg((const int4*)&g_csr[i + 4]);
        int4 p3 = __ldg((const int4*)&g_csr[i + 6]);
        uint4 r0 = *(const uint4*)(cur + (size_t)p0.x * NC + sub * 8);
        uint4 r1 = *(const uint4*)(cur + (size_t)p0.z * NC + sub * 8);
        uint4 r2 = *(const uint4*)(cur + (size_t)p1.x * NC + sub * 8);
        uint4 r3 = *(const uint4*)(cur + (size_t)p1.z * NC + sub * 8);
        uint4 r4 = *(const uint4*)(cur + (size_t)p2.x * NC + sub * 8);
        uint4 r5 = *(const uint4*)(cur + (size_t)p2.z * NC + sub * 8);
        uint4 r6 = *(const uint4*)(cur + (size_t)p3.x * NC + sub * 8);
        uint4 r7 = *(const uint4*)(cur + (size_t)p3.z * NC + sub * 8);
        mach(acc, r0, __float2half2_rn(__int_as_float(p0.y)));
        mach(acc, r1, __float2half2_rn(__int_as_float(p0.w)));
        mach(acc, r2, __float2half2_rn(__int_as_float(p1.y)));
        mach(acc, r3, __float2half2_rn(__int_as_float(p1.w)));
        mach(acc, r4, __float2half2_rn(__int_as_float(p2.y)));
        mach(acc, r5, __float2half2_rn(__int_as_float(p2.w)));
        mach(acc, r6, __float2half2_rn(__int_as_float(p3.y)));
        mach(acc, r7, __float2half2_rn(__int_as_float(p3.w)));
    }
    for (; i < e; i++) {
        int2 e0 = __ldg(&g_csr[i]);
        uint4 r0 = *(const uint4*)(cur + (size_t)e0.x * NC + sub * 8);
        mach(acc, r0, __float2half2_rn(__int_as_float(e0.y)));
    }

    size_t off = (size_t)row * NC + sub * 8;
    uint4 packed;
    __half2* ph = (__half2*)&packed;
    ph[0] = acc[0]; ph[1] = acc[1]; ph[2] = acc[2]; ph[3] = acc[3];
    *(uint4*)(next + off) = packed;
}

// ------- final: out = w0*x + sum_h w_h*cur_h, then log_softmax -------
__global__ void k_final(const float* __restrict__ x, float* __restrict__ dout) {
    int warp = (blockIdx.x * blockDim.x + threadIdx.x) >> 5;
    if (warp >= NN) return;
    int lane = threadIdx.x & 31;
    size_t off = (size_t)warp * NC + 2 * lane;

    float w[DEG];
    #pragma unroll
    for (int d = 0; d < DEG; d++) w[d] = __ldg(&g_weight[warp * DEG + d]);

    float2 xv = *(const float2*)(x + off);
    float tx = w[0] * xv.x, ty = w[0] * xv.y;
    #pragma unroll
    for (int h = 0; h < 5; h++) {
        float2 c = __half22float2(*(const __half2*)(g_curh[h] + off));
        tx += w[h + 1] * c.x;
        ty += w[h + 1] * c.y;
    }

    float m = fmaxf(tx, ty);
    #pragma unroll
    for (int o = 16; o; o >>= 1) m = fmaxf(m, __shfl_xor_sync(~0u, m, o));
    float s = __expf(tx - m) + __expf(ty - m);
    #pragma unroll
    for (int o = 16; o; o >>= 1) s += __shfl_xor_sync(~0u, s, o);
    float l = m + __logf(s);
    *(float2*)(dout + off) = make_float2(tx - l, ty - l);
}

// ---------------- launch ----------------
extern "C" void kernel_launch(void* const* d_in, const int* in_sizes, int n_in,
                              void* d_out, int out_size) {
    const float* x  = (const float*)d_in[0];
    const int*   er = (const int*)d_in[1];
    const int*   ec = (const int*)d_in[2];
    const float* ev = (const float*)d_in[3];
    const float* W1 = (const float*)d_in[4];
    const float* b1 = (const float*)d_in[5];
    const float* W2 = (const float*)d_in[6];
    const float* b2 = (const float*)d_in[7];
    float* out = (float*)d_out;

    k_hist<<<(EE + 255) / 256, 256>>>(er);                        // idx 0
    k_scan<<<SCAN_NB, SCAN_BS>>>(x);                              // idx 1
    k_scatter<<<(EE + 255) / 256, 256>>>(er, ec, ev);             // idx 2
    k_gating<<<(NN * 32 + 255) / 256, 256>>>(x, W1, b1, W2, b2);  // idx 3 <- profiled

    k_spmm<<<(NN * 8 + 255) / 256, 256>>>(-1, 0);                 // idx 4
    k_spmm<<<(NN * 8 + 255) / 256, 256>>>(0, 1);                  // idx 5
    k_spmm<<<(NN * 8 + 255) / 256, 256>>>(1, 2);                  // idx 6
    k_spmm<<<(NN * 8 + 255) / 256, 256>>>(2, 3);                  // idx 7
    k_spmm<<<(NN * 8 + 255) / 256, 256>>>(3, 4);                  // idx 8

    k_final<<<(NN * 32 + 255) / 256, 256>>>(x, out);              // idx 9
}

// round 9
// speedup vs baseline: 2.1390x; 1.8919x over previous
#include <cuda_runtime.h>
#include <cuda_fp16.h>
#include <cstdint>

#define NN 100000
#define EE 3200000
#define NC 64
#define TOPK 16
#define NHID 128
#define DEG 6
#define SCAN_BS 1024
#define SCAN_NB ((NN + SCAN_BS - 1) / SCAN_BS)   // 98

// ---------------- device scratch (static allocation only) ----------------
__device__ int   g_count[NN];            // zero at load; self-restored each call
__device__ int   g_rowstart[NN + 1];
__device__ int   g_cursor[NN];
__device__ int   g_aggr[SCAN_NB];
__device__ int   g_incl[SCAN_NB];
__device__ int   g_flag[SCAN_NB];
__device__ __align__(16) int2 g_csr[EE]; // (col, val bits fp32)
__device__ __align__(16) __half g_xh[(size_t)NN * NC];
__device__ __align__(16) __half g_curh[5][(size_t)NN * NC];
__device__ float g_weight[NN * DEG];
__device__ float g_W1T[TOPK * NHID];     // transposed W1: [k][r]

// ---------------- prep: transpose W1 (8KB, trivial) ----------------
__global__ void k_prep(const float* __restrict__ W1) {
    int i = threadIdx.x + blockIdx.x * blockDim.x;
    if (i < NHID * TOPK) {
        int r = i / TOPK, k = i % TOPK;
        g_W1T[k * NHID + r] = W1[i];
    }
}

// ---------------- hist (+ reset scan flags for this call) ----------------
__global__ void k_hist(const int* __restrict__ er) {
    int i = blockIdx.x * blockDim.x + threadIdx.x;
    if (i < SCAN_NB) g_flag[i] = 0;
    if (i < EE) atomicAdd(&g_count[er[i]], 1);
}

// ------- single-pass scan (decoupled lookback) + x -> fp16 conversion -------
__global__ void __launch_bounds__(SCAN_BS) k_scan(const float* __restrict__ x) {
    __shared__ int sh[SCAN_BS];
    __shared__ int s_prefix;
    int b = blockIdx.x, t = threadIdx.x;
    int i = b * SCAN_BS + t;

    int v = (i < NN) ? g_count[i] : 0;
    if (i < NN) g_count[i] = 0;
    sh[t] = v;
    __syncthreads();
    for (int o = 1; o < SCAN_BS; o <<= 1) {
        int tt = (t >= o) ? sh[t - o] : 0;
        __syncthreads();
        sh[t] += tt;
        __syncthreads();
    }
    int total = sh[SCAN_BS - 1];

    if (t == 0) {
        g_aggr[b] = total;
        __threadfence();
        g_flag[b] = 1;
        int pfx = 0;
        for (int j = b - 1; j >= 0; j--) {
            int f;
            do { f = ((volatile int*)g_flag)[j]; } while (f == 0);
            if (f == 2) { pfx += ((volatile int*)g_incl)[j]; break; }
            pfx += ((volatile int*)g_aggr)[j];
        }
        g_incl[b] = pfx + total;
        __threadfence();
        g_flag[b] = 2;
        s_prefix = pfx;
        if (b == 0) g_rowstart[NN] = EE;
    }
    __syncthreads();

    if (i < NN) {
        int r = s_prefix + sh[t] - v;
        g_rowstart[i] = r;
        g_cursor[i]   = r;
    }

    // fused: convert this block's rows of x to fp16
    size_t base = (size_t)b * SCAN_BS * NC;
    int nrows = NN - b * SCAN_BS;
    if (nrows > SCAN_BS) nrows = SCAN_BS;
    if (nrows > 0) {
        int nquad = nrows * NC / 4;
        for (int k = t; k < nquad; k += SCAN_BS) {
            float4 f = *(const float4*)(x + base + (size_t)k * 4);
            *(__half2*)(g_xh + base + (size_t)k * 4)     = __floats2half2_rn(f.x, f.y);
            *(__half2*)(g_xh + base + (size_t)k * 4 + 2) = __floats2half2_rn(f.z, f.w);
        }
    }
}

// ---------------- scatter ----------------
__global__ void k_scatter(const int* __restrict__ er,
                          const int* __restrict__ ec,
                          const float* __restrict__ ev) {
    int i = blockIdx.x * blockDim.x + threadIdx.x;
    if (i >= EE) return;
    int pos = atomicAdd(&g_cursor[er[i]], 1);
    g_csr[pos] = make_int2(ec[i], __float_as_int(ev[i]));
}

// ------- gating: softmax -> bitonic top16 -> MLP (coalesced W1T) -> weights -------
__global__ void k_gating(const float* __restrict__ x,
                         const float* __restrict__ b1,
                         const float* __restrict__ W2, const float* __restrict__ b2) {
    int warp = (blockIdx.x * blockDim.x + threadIdx.x) >> 5;
    if (warp >= NN) return;
    int lane = threadIdx.x & 31;

    float2 xv = *(const float2*)(x + (size_t)warp * NC + 2 * lane);

    // softmax over 64
    float m = fmaxf(xv.x, xv.y);
    #pragma unroll
    for (int o = 16; o; o >>= 1) m = fmaxf(m, __shfl_xor_sync(~0u, m, o));
    float e0 = __expf(xv.x - m), e1 = __expf(xv.y - m);
    float s = e0 + e1;
    #pragma unroll
    for (int o = 16; o; o >>= 1) s += __shfl_xor_sync(~0u, s, o);
    float inv = 1.0f / s;
    float a = e0 * inv, b = e1 * inv;   // vidx 2*lane, 2*lane+1

    // bitonic sort of 64 values, descending (values only)
    #pragma unroll
    for (int k = 2; k <= 64; k <<= 1) {
        #pragma unroll
        for (int j = k >> 1; j > 0; j >>= 1) {
            if (j >= 2) {
                float pa = __shfl_xor_sync(~0u, a, j >> 1);
                float pb = __shfl_xor_sync(~0u, b, j >> 1);
                int i0 = 2 * lane, i1 = 2 * lane + 1;
                bool up  = ((i0 & k) != 0);
                bool km0 = (((i0 & j) == 0) != up);
                bool km1 = (((i1 & j) == 0) != up);
                a = km0 ? fmaxf(a, pa) : fminf(a, pa);
                b = km1 ? fmaxf(b, pb) : fminf(b, pb);
            } else {
                bool up = (((2 * lane) & k) != 0);
                float mx = fmaxf(a, b), mn = fminf(a, b);
                a = up ? mn : mx;
                b = up ? mx : mn;
            }
        }
    }

    // broadcast top-16 (vidx 0..15 live in lanes 0..7)
    float tk[TOPK];
    #pragma unroll
    for (int q = 0; q < 8; q++) {
        tk[2 * q]     = __shfl_sync(~0u, a, q);
        tk[2 * q + 1] = __shfl_sync(~0u, b, q);
    }

    // layer 1: coalesced W1T reads (lane-consecutive addresses)
    float h[4];
    #pragma unroll
    for (int j = 0; j < 4; j++) h[j] = b1[lane + 32 * j];
    #pragma unroll
    for (int k = 0; k < TOPK; k++) {
        #pragma unroll
        for (int j = 0; j < 4; j++)
            h[j] += tk[k] * __ldg(&g_W1T[k * NHID + lane + 32 * j]);
    }
    #pragma unroll
    for (int j = 0; j < 4; j++) h[j] = (h[j] >= 0.0f) ? h[j] : 0.1f * h[j];

    // layer 2 (already coalesced)
    float lg[DEG];
    #pragma unroll
    for (int d = 0; d < DEG; d++) {
        float acc = 0.0f;
        #pragma unroll
        for (int j = 0; j < 4; j++) acc += h[j] * __ldg(&W2[d * NHID + lane + 32 * j]);
        #pragma unroll
        for (int o = 16; o; o >>= 1) acc += __shfl_xor_sync(~0u, acc, o);
        lg[d] = acc + b2[d];
    }

    // softmax over 6 hops
    float mm = lg[0];
    #pragma unroll
    for (int d = 1; d < DEG; d++) mm = fmaxf(mm, lg[d]);
    float ss = 0.0f;
    #pragma unroll
    for (int d = 0; d < DEG; d++) { lg[d] = __expf(lg[d] - mm); ss += lg[d]; }
    float invs = 1.0f / ss;
    if (lane < DEG) g_weight[warp * DEG + lane] = lg[lane] * invs;
}

// -------- SpMM gather: fp16 features, HFMA2 fp16 accumulation --------
__device__ __forceinline__ void mach(__half2* acc, uint4 raw, __half2 vh) {
    acc[0] = __hfma2(*(__half2*)&raw.x, vh, acc[0]);
    acc[1] = __hfma2(*(__half2*)&raw.y, vh, acc[1]);
    acc[2] = __hfma2(*(__half2*)&raw.z, vh, acc[2]);
    acc[3] = __hfma2(*(__half2*)&raw.w, vh, acc[3]);
}

__global__ void __launch_bounds__(256) k_spmm(int srcsel, int dstsel) {
    int gtid = blockIdx.x * blockDim.x + threadIdx.x;
    int row = gtid >> 3;                 // 8 lanes per row
    if (row >= NN) return;
    int sub = threadIdx.x & 7;

    const __half* __restrict__ cur = (srcsel < 0) ? g_xh : g_curh[srcsel];
    __half* __restrict__ next = g_curh[dstsel];

    int s = g_rowstart[row], e = g_rowstart[row + 1];
    __half2 acc[4];
    #pragma unroll
    for (int j = 0; j < 4; j++) acc[j] = __floats2half2_rn(0.f, 0.f);

    int i = s;
    if ((i & 1) && i < e) {              // peel to 16B boundary for int4 csr loads
        int2 e0 = __ldg(&g_csr[i]);
        uint4 r0 = *(const uint4*)(cur + (size_t)e0.x * NC + sub * 8);
        mach(acc, r0, __float2half2_rn(__int_as_float(e0.y)));
        i++;
    }
    for (; i + 8 <= e; i += 8) {
        int4 p0 = __ldg((const int4*)&g_csr[i]);
        int4 p1 = __ldg((const int4*)&g_csr[i + 2]);
        int4 p2 = __ldg((const int4*)&g_csr[i + 4]);
        int4 p3 = __ldg((const int4*)&g_csr[i + 6]);
        uint4 r0 = *(const uint4*)(cur + (size_t)p0.x * NC + sub * 8);
        uint4 r1 = *(const uint4*)(cur + (size_t)p0.z * NC + sub * 8);
        uint4 r2 = *(const uint4*)(cur + (size_t)p1.x * NC + sub * 8);
        uint4 r3 = *(const uint4*)(cur + (size_t)p1.z * NC + sub * 8);
        uint4 r4 = *(const uint4*)(cur + (size_t)p2.x * NC + sub * 8);
        uint4 r5 = *(const uint4*)(cur + (size_t)p2.z * NC + sub * 8);
        uint4 r6 = *(const uint4*)(cur + (size_t)p3.x * NC + sub * 8);
        uint4 r7 = *(const uint4*)(cur + (size_t)p3.z * NC + sub * 8);
        mach(acc, r0, __float2half2_rn(__int_as_float(p0.y)));
        mach(acc, r1, __float2half2_rn(__int_as_float(p0.w)));
        mach(acc, r2, __float2half2_rn(__int_as_float(p1.y)));
        mach(acc, r3, __float2half2_rn(__int_as_float(p1.w)));
        mach(acc, r4, __float2half2_rn(__int_as_float(p2.y)));
        mach(acc, r5, __float2half2_rn(__int_as_float(p2.w)));
        mach(acc, r6, __float2half2_rn(__int_as_float(p3.y)));
        mach(acc, r7, __float2half2_rn(__int_as_float(p3.w)));
    }
    for (; i < e; i++) {
        int2 e0 = __ldg(&g_csr[i]);
        uint4 r0 = *(const uint4*)(cur + (size_t)e0.x * NC + sub * 8);
        mach(acc, r0, __float2half2_rn(__int_as_float(e0.y)));
    }

    size_t off = (size_t)row * NC + sub * 8;
    uint4 packed;
    __half2* ph = (__half2*)&packed;
    ph[0] = acc[0]; ph[1] = acc[1]; ph[2] = acc[2]; ph[3] = acc[3];
    *(uint4*)(next + off) = packed;
}

// ------- final: out = w0*x + sum_h w_h*cur_h, then log_softmax -------
__global__ void k_final(const float* __restrict__ x, float* __restrict__ dout) {
    int warp = (blockIdx.x * blockDim.x + threadIdx.x) >> 5;
    if (warp >= NN) return;
    int lane = threadIdx.x & 31;
    size_t off = (size_t)warp * NC + 2 * lane;

    float w[DEG];
    #pragma unroll
    for (int d = 0; d < DEG; d++) w[d] = __ldg(&g_weight[warp * DEG + d]);

    float2 xv = *(const float2*)(x + off);
    float tx = w[0] * xv.x, ty = w[0] * xv.y;
    #pragma unroll
    for (int h = 0; h < 5; h++) {
        float2 c = __half22float2(*(const __half2*)(g_curh[h] + off));
        tx += w[h + 1] * c.x;
        ty += w[h + 1] * c.y;
    }

    float m = fmaxf(tx, ty);
    #pragma unroll
    for (int o = 16; o; o >>= 1) m = fmaxf(m, __shfl_xor_sync(~0u, m, o));
    float s = __expf(tx - m) + __expf(ty - m);
    #pragma unroll
    for (int o = 16; o; o >>= 1) s += __shfl_xor_sync(~0u, s, o);
    float l = m + __logf(s);
    *(float2*)(dout + off) = make_float2(tx - l, ty - l);
}

// ---------------- launch ----------------
extern "C" void kernel_launch(void* const* d_in, const int* in_sizes, int n_in,
                              void* d_out, int out_size) {
    const float* x  = (const float*)d_in[0];
    const int*   er = (const int*)d_in[1];
    const int*   ec = (const int*)d_in[2];
    const float* ev = (const float*)d_in[3];
    const float* W1 = (const float*)d_in[4];
    const float* b1 = (const float*)d_in[5];
    const float* W2 = (const float*)d_in[6];
    const float* b2 = (const float*)d_in[7];
    float* out = (float*)d_out;

    k_prep<<<8, 256>>>(W1);                                        // idx 0
    k_hist<<<(EE + 255) / 256, 256>>>(er);                         // idx 1
    k_scan<<<SCAN_NB, SCAN_BS>>>(x);                               // idx 2
    k_gating<<<(NN * 32 + 255) / 256, 256>>>(x, b1, W2, b2);       // idx 3 <- profiled
    k_scatter<<<(EE + 255) / 256, 256>>>(er, ec, ev);              // idx 4

    k_spmm<<<(NN * 8 + 255) / 256, 256>>>(-1, 0);                  // idx 5
    k_spmm<<<(NN * 8 + 255) / 256, 256>>>(0, 1);                   // idx 6
    k_spmm<<<(NN * 8 + 255) / 256, 256>>>(1, 2);                   // idx 7
    k_spmm<<<(NN * 8 + 255) / 256, 256>>>(2, 3);                   // idx 8
    k_spmm<<<(NN * 8 + 255) / 256, 256>>>(3, 4);                   // idx 9

    k_final<<<(NN * 32 + 255) / 256, 256>>>(x, out);               // idx 10
}